// round 11
// baseline (speedup 1.0000x reference)
#include <cuda_runtime.h>
#include <cuda_bf16.h>
#include <float.h>

#define NTOK   4096
#define DMODEL 320
#define HEADS  8
#define DH     40
#define NPHASE 3
#define KTILE  64
#define QBLK   64
#define UT     4
#define MAXU   1152
#define MAXSPL 16

typedef unsigned long long ull;

#define LDSM_X4(r0, r1, r2, r3, addr) \
    asm volatile("ldmatrix.sync.aligned.m8n8.x4.shared.b16 {%0,%1,%2,%3}, [%4];" \
        : "=r"(r0), "=r"(r1), "=r"(r2), "=r"(r3) : "r"(addr))
#define LDSM_X4T(r0, r1, r2, r3, addr) \
    asm volatile("ldmatrix.sync.aligned.m8n8.x4.trans.shared.b16 {%0,%1,%2,%3}, [%4];" \
        : "=r"(r0), "=r"(r1), "=r"(r2), "=r"(r3) : "r"(addr))
#define MMA_BF16(c, a, b) \
    asm volatile("mma.sync.aligned.m16n8k16.row.col.f32.bf16.bf16.f32 " \
        "{%0,%1,%2,%3}, {%4,%5,%6,%7}, {%8,%9}, {%0,%1,%2,%3};" \
        : "+f"((c)[0]), "+f"((c)[1]), "+f"((c)[2]), "+f"((c)[3]) \
        : "r"((a)[0]), "r"((a)[1]), "r"((a)[2]), "r"((a)[3]), \
          "r"((b)[0]), "r"((b)[1]))

// ---------------- scratch (__device__ globals; no allocation allowed) -------
__device__ float g_q[HEADS * NTOK * DH];
__device__ float g_k[HEADS * NTOK * DH];
__device__ float g_v[HEADS * NTOK * DH];
__device__ float g_o[NTOK * DMODEL];

// planning data
__device__ int g_grp_cnt[8], g_grp_off[8];
__device__ int g_qidx[NTOK];
__device__ int g_kcnt[8];
__device__ int g_kidx[8][NTOK];
__device__ int g_nsplit[8];
__device__ int g_u_sig[MAXU], g_u_qoff[MAXU], g_u_qend[MAXU];
__device__ int g_u_t0[MAXU], g_u_t1[MAXU], g_u_spl[MAXU];
__device__ int g_nunits;

// compacted bf16 split K/V per (sig, head):
// K transposed d-major: [sh][d(48)][jc(4096)]   V row-major: [sh][jc][48]
#define KD 48
__device__ __nv_bfloat16 g_kth[7 * HEADS * KD * NTOK];
__device__ __nv_bfloat16 g_ktl[7 * HEADS * KD * NTOK];
__device__ __nv_bfloat16 g_vh[7 * HEADS * NTOK * KD];
__device__ __nv_bfloat16 g_vl[7 * HEADS * NTOK * KD];

__device__ float g_meanv[HEADS * DH];
__device__ float g_mvpart[16][HEADS * DH];

// split partials: indexed [spl][head][ql]
__device__ float g_pacc[MAXSPL * HEADS * NTOK * DH];
__device__ float g_pm[MAXSPL * HEADS * NTOK];
__device__ float g_pl[MAXSPL * HEADS * NTOK];

__device__ __forceinline__ float ex2(float x) {
    float r;
    asm("ex2.approx.ftz.f32 %0, %1;" : "=f"(r) : "f"(x));
    return r;
}
__device__ __forceinline__ unsigned s2u(const void* p) {
    return (unsigned)__cvta_generic_to_shared(p);
}
__device__ __forceinline__ unsigned packbf(float lo, float hi) {
    unsigned r;
    asm("cvt.rn.bf16x2.f32 %0, %1, %2;" : "=r"(r) : "f"(hi), "f"(lo));
    return r;
}

// ---------------------------------------------------------------------------
// Plan kernel (mask packing fused; proven R10 version)
// ---------------------------------------------------------------------------
__global__ __launch_bounds__(256) void plan_kernel(const float* __restrict__ gm) {
    __shared__ unsigned smb[NPHASE * (NTOK / 32)];
    __shared__ int sq[8][256];
    __shared__ int sk[8][256];
    __shared__ int base_q[8];
    const int t = threadIdx.x;

    {
        unsigned bits = 0;
        #pragma unroll 8
        for (int b = 0; b < 32; b++)
            if (gm[t * 32 + b] != 0.0f) bits |= (1u << b);
        smb[t] = bits;
        if (t < 128) {
            unsigned bits2 = 0;
            #pragma unroll 8
            for (int b = 0; b < 32; b++)
                if (gm[(256 + t) * 32 + b] != 0.0f) bits2 |= (1u << b);
            smb[256 + t] = bits2;
        }
    }
    __syncthreads();

    unsigned bits_arr[16];
    int cq[8], ck[8];
    #pragma unroll
    for (int s = 0; s < 8; s++) { cq[s] = 0; ck[s] = 0; }

    for (int u = 0; u < 16; u++) {
        int i = t * 16 + u;
        unsigned b = 0;
        #pragma unroll
        for (int p = 0; p < NPHASE; p++)
            b |= ((smb[p * 128 + (i >> 5)] >> (i & 31)) & 1u) << p;
        bits_arr[u] = b;
        cq[b]++;
        #pragma unroll
        for (int s = 1; s < 8; s++)
            if (b & (unsigned)s) ck[s]++;
    }
    #pragma unroll
    for (int s = 0; s < 8; s++) { sq[s][t] = cq[s]; sk[s][t] = ck[s]; }
    __syncthreads();

    for (int g = 0; g < 15; g++) {
        int* arr = (g < 8) ? sq[g] : sk[g - 7];
        for (int off = 1; off < 256; off <<= 1) {
            int u = (t >= off) ? arr[t - off] : 0;
            __syncthreads();
            arr[t] += u;
            __syncthreads();
        }
    }

    if (t == 0) {
        int acc = 0;
        for (int s = 0; s < 8; s++) {
            base_q[s] = acc;
            g_grp_off[s] = acc;
            int tot = sq[s][255];
            g_grp_cnt[s] = tot;
            acc += tot;
        }
        int nu = 0;
        for (int s = 1; s < 8; s++) {
            int kc = sk[s][255];
            g_kcnt[s] = kc;
            int cnt = sq[s][255], off = base_q[s];
            int tiles = (kc + KTILE - 1) / KTILE;
            int ns = (tiles + UT - 1) / UT;
            g_nsplit[s] = ns;
            for (int b = 0; b * QBLK < cnt; b++) {
                for (int sp = 0; sp < ns; sp++) {
                    g_u_sig[nu] = s;
                    g_u_qoff[nu] = off + b * QBLK;
                    g_u_qend[nu] = off + cnt;
                    g_u_t0[nu] = sp * UT * KTILE;
                    int t1 = (sp + 1) * UT * KTILE;
                    g_u_t1[nu] = (t1 < kc) ? t1 : kc;
                    g_u_spl[nu] = sp;
                    nu++;
                }
            }
        }
        g_nunits = nu;
    }
    __syncthreads();

    int qcur[8], kcur[8];
    #pragma unroll
    for (int s = 0; s < 8; s++) {
        qcur[s] = base_q[s] + sq[s][t] - cq[s];
        kcur[s] = sk[s][t] - ck[s];
    }
    for (int u = 0; u < 16; u++) {
        int i = t * 16 + u;
        unsigned b = bits_arr[u];
        g_qidx[qcur[b]++] = i;
        #pragma unroll
        for (int s = 1; s < 8; s++)
            if (b & (unsigned)s) g_kidx[s][kcur[s]++] = i;
    }
}

// ---------------------------------------------------------------------------
// QKV projection via bf16 split-precision MMA (proven R10 version).
// ---------------------------------------------------------------------------
#define SKA 40
#define SNB 72

__global__ __launch_bounds__(256) void qkv_gemm(
    const float* __restrict__ X,
    const float* __restrict__ Wq, const float* __restrict__ Wk,
    const float* __restrict__ Wv)
{
    const float* W = (blockIdx.z == 0) ? Wq : (blockIdx.z == 1) ? Wk : Wv;
    float* Dst = (blockIdx.z == 0) ? g_q : (blockIdx.z == 1) ? g_k : g_v;

    __shared__ __nv_bfloat16 Ah[128 * SKA], Al[128 * SKA];
    __shared__ __nv_bfloat16 Bh[32 * SNB],  Bl[32 * SNB];

    const int tid  = threadIdx.x;
    const int lane = tid & 31;
    const int wid  = tid >> 5;
    const int warp_m = wid >> 1;
    const int warp_n = wid & 1;
    const int m0 = blockIdx.y * 128;
    const int n0 = blockIdx.x * 64;
    const int quad = lane >> 3, rr = lane & 7;

    float c[2][4][4];
    #pragma unroll
    for (int mf = 0; mf < 2; mf++)
        #pragma unroll
        for (int nf = 0; nf < 4; nf++)
            #pragma unroll
            for (int r = 0; r < 4; r++) c[mf][nf][r] = 0.0f;

    const int arow = tid >> 1, ahalf = (tid & 1) * 16;
    const int brow = tid >> 3, bcol = (tid & 7) * 8;

    unsigned aAh[2], aAl[2];
    #pragma unroll
    for (int mf = 0; mf < 2; mf++) {
        int mrow = warp_m * 32 + mf * 16 + (quad & 1) * 8 + rr;
        int kcol = (quad >> 1) * 8;
        aAh[mf] = s2u(&Ah[mrow * SKA + kcol]);
        aAl[mf] = s2u(&Al[mrow * SKA + kcol]);
    }
    unsigned aBh[2], aBl[2];
    #pragma unroll
    for (int nf2 = 0; nf2 < 2; nf2++) {
        int krow = (quad & 1) * 8 + rr;
        int ncol = warp_n * 32 + nf2 * 16 + (quad >> 1) * 8;
        aBh[nf2] = s2u(&Bh[krow * SNB + ncol]);
        aBl[nf2] = s2u(&Bl[krow * SNB + ncol]);
    }

    for (int k0 = 0; k0 < DMODEL; k0 += 32) {
        float4 av[4], wv[2];
        const float4* asrc = (const float4*)(X + (size_t)(m0 + arow) * DMODEL + k0 + ahalf);
        #pragma unroll
        for (int j = 0; j < 4; j++) av[j] = asrc[j];
        const float4* wsrc = (const float4*)(W + (size_t)(k0 + brow) * DMODEL + n0 + bcol);
        #pragma unroll
        for (int j = 0; j < 2; j++) wv[j] = wsrc[j];
        __syncthreads();

        #pragma unroll
        for (int j = 0; j < 4; j++) {
            float f[4] = {av[j].x, av[j].y, av[j].z, av[j].w};
            #pragma unroll
            for (int e = 0; e < 4; e += 2) {
                __nv_bfloat16 h0 = __float2bfloat16_rn(f[e]);
                __nv_bfloat16 h1 = __float2bfloat16_rn(f[e + 1]);
                __nv_bfloat16 l0 = __float2bfloat16_rn(f[e] - __bfloat162float(h0));
                __nv_bfloat16 l1 = __float2bfloat16_rn(f[e + 1] - __bfloat162float(h1));
                int off = arow * SKA + ahalf + j * 4 + e;
                *(__nv_bfloat162*)&Ah[off] = __nv_bfloat162(h0, h1);
                *(__nv_bfloat162*)&Al[off] = __nv_bfloat162(l0, l1);
            }
        }
        #pragma unroll
        for (int j = 0; j < 2; j++) {
            float f[4] = {wv[j].x, wv[j].y, wv[j].z, wv[j].w};
            #pragma unroll
            for (int e = 0; e < 4; e += 2) {
                __nv_bfloat16 h0 = __float2bfloat16_rn(f[e]);
                __nv_bfloat16 h1 = __float2bfloat16_rn(f[e + 1]);
                __nv_bfloat16 l0 = __float2bfloat16_rn(f[e] - __bfloat162float(h0));
                __nv_bfloat16 l1 = __float2bfloat16_rn(f[e + 1] - __bfloat162float(h1));
                int off = brow * SNB + bcol + j * 4 + e;
                *(__nv_bfloat162*)&Bh[off] = __nv_bfloat162(h0, h1);
                *(__nv_bfloat162*)&Bl[off] = __nv_bfloat162(l0, l1);
            }
        }
        __syncthreads();

        #pragma unroll
        for (int ks = 0; ks < 2; ks++) {
            const unsigned koffA = ks * 16 * 2;
            const unsigned koffB = (unsigned)(ks * 16 * SNB * 2);
            unsigned ah[2][4], al[2][4];
            #pragma unroll
            for (int mf = 0; mf < 2; mf++) {
                LDSM_X4(ah[mf][0], ah[mf][1], ah[mf][2], ah[mf][3], aAh[mf] + koffA);
                LDSM_X4(al[mf][0], al[mf][1], al[mf][2], al[mf][3], aAl[mf] + koffA);
            }
            unsigned bh[4][2], bl[4][2];
            #pragma unroll
            for (int nf2 = 0; nf2 < 2; nf2++) {
                unsigned r0, r1, r2, r3;
                LDSM_X4T(r0, r1, r2, r3, aBh[nf2] + koffB);
                bh[nf2 * 2][0] = r0;  bh[nf2 * 2][1] = r1;
                bh[nf2 * 2 + 1][0] = r2;  bh[nf2 * 2 + 1][1] = r3;
                LDSM_X4T(r0, r1, r2, r3, aBl[nf2] + koffB);
                bl[nf2 * 2][0] = r0;  bl[nf2 * 2][1] = r1;
                bl[nf2 * 2 + 1][0] = r2;  bl[nf2 * 2 + 1][1] = r3;
            }
            #pragma unroll
            for (int mf = 0; mf < 2; mf++)
                #pragma unroll
                for (int nf = 0; nf < 4; nf++) {
                    MMA_BF16(c[mf][nf], ah[mf], bh[nf]);
                    MMA_BF16(c[mf][nf], ah[mf], bl[nf]);
                    MMA_BF16(c[mf][nf], al[mf], bh[nf]);
                }
        }
    }

    #pragma unroll
    for (int mf = 0; mf < 2; mf++) {
        #pragma unroll
        for (int nf = 0; nf < 4; nf++) {
            int row = m0 + warp_m * 32 + mf * 16 + (lane >> 2);
            int col = n0 + warp_n * 32 + nf * 8 + (lane & 3) * 2;
            int h = col / DH, d = col % DH;
            float* base = Dst + (size_t)h * NTOK * DH;
            *(float2*)&base[(size_t)row * DH + d] =
                make_float2(c[mf][nf][0], c[mf][nf][1]);
            *(float2*)&base[(size_t)(row + 8) * DH + d] =
                make_float2(c[mf][nf][2], c[mf][nf][3]);
        }
    }
}

// ---------------------------------------------------------------------------
// Gather: compacted bf16 split K (d-major) and V (row-major), zero-padded.
// One thread per compacted key row. grid (32, 7, 8), 128 threads.
// ---------------------------------------------------------------------------
__global__ __launch_bounds__(128) void gather_kernel() {
    const int sig = blockIdx.y + 1;
    const int head = blockIdx.z;
    const int kc = g_kcnt[sig];
    const int pad = (kc + KTILE - 1) & ~(KTILE - 1);
    const int jc = blockIdx.x * 128 + threadIdx.x;
    if (jc >= pad) return;
    const bool valid = jc < kc;
    const int j = valid ? g_kidx[sig][jc] : 0;

    const int sh = (sig - 1) * HEADS + head;
    __nv_bfloat16* kth = g_kth + (size_t)sh * KD * NTOK;
    __nv_bfloat16* ktl = g_ktl + (size_t)sh * KD * NTOK;
    __nv_bfloat16* vh = g_vh + (size_t)sh * NTOK * KD + (size_t)jc * KD;
    __nv_bfloat16* vl = g_vl + (size_t)sh * NTOK * KD + (size_t)jc * KD;

    const float* krow = g_k + ((size_t)head * NTOK + j) * DH;
    const float* vrow = g_v + ((size_t)head * NTOK + j) * DH;
    const __nv_bfloat16 z = __float2bfloat16_rn(0.0f);

    #pragma unroll
    for (int c8 = 0; c8 < 5; c8++) {
        #pragma unroll
        for (int e = 0; e < 8; e++) {
            int d = c8 * 8 + e;
            float kf = valid ? krow[d] : 0.0f;
            float vf = valid ? vrow[d] : 0.0f;
            __nv_bfloat16 kh = __float2bfloat16_rn(kf);
            __nv_bfloat16 kl = __float2bfloat16_rn(kf - __bfloat162float(kh));
            __nv_bfloat16 vhh = __float2bfloat16_rn(vf);
            __nv_bfloat16 vll = __float2bfloat16_rn(vf - __bfloat162float(vhh));
            kth[(size_t)d * NTOK + jc] = kh;
            ktl[(size_t)d * NTOK + jc] = kl;
            vh[d] = vhh;
            vl[d] = vll;
        }
    }
    #pragma unroll
    for (int d = DH; d < KD; d++) {
        kth[(size_t)d * NTOK + jc] = z;
        ktl[(size_t)d * NTOK + jc] = z;
        vh[d] = z;
        vl[d] = z;
    }
}

// ---------------------------------------------------------------------------
// Per-head V column mean: two-stage
// ---------------------------------------------------------------------------
__global__ __launch_bounds__(320) void meanv1_kernel() {
    __shared__ float red[320];
    const int head = blockIdx.x;
    const int chunk = blockIdx.y;
    const int t = threadIdx.x;
    const int d = t % DH, r = t / DH;
    float s = 0.0f;
    const int j0 = chunk * 256;
    for (int j = j0 + r; j < j0 + 256; j += 8)
        s += g_v[((size_t)head * NTOK + j) * DH + d];
    red[t] = s;
    __syncthreads();
    if (r == 0) {
        float tot = 0.0f;
        #pragma unroll
        for (int rr = 0; rr < 8; rr++) tot += red[rr * DH + d];
        g_mvpart[chunk][head * DH + d] = tot;
    }
}

__global__ __launch_bounds__(320) void meanv2_kernel() {
    const int i = threadIdx.x;
    float s = 0.0f;
    #pragma unroll
    for (int c = 0; c < 16; c++) s += g_mvpart[c][i];
    g_meanv[i] = s * (1.0f / (float)NTOK);
}

// ---------------------------------------------------------------------------
// Tensor-core flash attention. 128 threads = 4 warps; each warp owns 16
// query rows. 64q x 64k tiles, bf16 split precision, log2-domain softmax.
// ---------------------------------------------------------------------------
#define SQ 56   // Q smem row stride (bf16)
#define SKT 72  // K-transposed smem row stride (bf16): 64 + 8
#define SV 56   // V smem row stride (bf16): 48 + 8

__global__ __launch_bounds__(128) void attn_kernel() {
    if (blockIdx.x >= g_nunits) return;

    __shared__ __nv_bfloat16 Qh[64 * SQ], Ql[64 * SQ];
    __shared__ __nv_bfloat16 Kth[KD * SKT], Ktl[KD * SKT];
    __shared__ __nv_bfloat16 Vh[64 * SV], Vl[64 * SV];

    const int tid  = threadIdx.x;
    const int lane = tid & 31;
    const int warp = tid >> 5;
    const int quad = lane >> 3, rr = lane & 7;
    const int head = blockIdx.y;
    const int uix  = blockIdx.x;
    const int sig  = g_u_sig[uix];
    const int qoff = g_u_qoff[uix];
    const int qend = g_u_qend[uix];
    const int t_start = g_u_t0[uix];
    const int t_end   = g_u_t1[uix];
    const int spl  = g_u_spl[uix];
    const float scale = 0.15811388300841898f * 1.4426950408889634f;

    const int sh = (sig - 1) * HEADS + head;
    const __nv_bfloat16* gkh = g_kth + (size_t)sh * KD * NTOK;
    const __nv_bfloat16* gkl = g_ktl + (size_t)sh * KD * NTOK;
    const __nv_bfloat16* gvh = g_vh + (size_t)sh * NTOK * KD;
    const __nv_bfloat16* gvl = g_vl + (size_t)sh * NTOK * KD;

    // ---- load Q tile (scaled, split) ----
    for (int idx = tid; idx < 64 * 10; idx += 128) {
        int q = idx / 10, c4 = idx % 10;
        int qlc = qoff + q;
        if (qlc >= qend) qlc = qoff;
        int qi = g_qidx[qlc];
        float4 v = *(const float4*)(g_q + ((size_t)head * NTOK + qi) * DH + c4 * 4);
        float f[4] = {v.x * scale, v.y * scale, v.z * scale, v.w * scale};
        #pragma unroll
        for (int e = 0; e < 4; e += 2) {
            __nv_bfloat16 h0 = __float2bfloat16_rn(f[e]);
            __nv_bfloat16 h1 = __float2bfloat16_rn(f[e + 1]);
            __nv_bfloat16 l0 = __float2bfloat16_rn(f[e] - __bfloat162float(h0));
            __nv_bfloat16 l1 = __float2bfloat16_rn(f[e + 1] - __bfloat162float(h1));
            int off = q * SQ + c4 * 4 + e;
            *(__nv_bfloat162*)&Qh[off] = __nv_bfloat162(h0, h1);
            *(__nv_bfloat162*)&Ql[off] = __nv_bfloat162(l0, l1);
        }
    }
    // zero Q pad cols 40..47 (NaN safety for k-dim padding)
    for (int idx = tid; idx < 64 * 4; idx += 128) {
        int q = idx >> 2, e = (idx & 3) * 2;
        *(__nv_bfloat162*)&Qh[q * SQ + 40 + e] = __nv_bfloat162(0.f, 0.f);
        *(__nv_bfloat162*)&Ql[q * SQ + 40 + e] = __nv_bfloat162(0.f, 0.f);
    }

    // ldmatrix base addresses (mirror proven qkv patterns)
    const unsigned aQh = s2u(&Qh[(warp * 16 + (quad & 1) * 8 + rr) * SQ + (quad >> 1) * 8]);
    const unsigned aQl = s2u(&Ql[(warp * 16 + (quad & 1) * 8 + rr) * SQ + (quad >> 1) * 8]);
    const unsigned aKh = s2u(&Kth[((quad & 1) * 8 + rr) * SKT + (quad >> 1) * 8]);
    const unsigned aKl = s2u(&Ktl[((quad & 1) * 8 + rr) * SKT + (quad >> 1) * 8]);
    const unsigned aVh = s2u(&Vh[((quad & 1) * 8 + rr) * SV + (quad >> 1) * 8]);
    const unsigned aVl = s2u(&Vl[((quad & 1) * 8 + rr) * SV + (quad >> 1) * 8]);

    float m0 = -FLT_MAX, m1 = -FLT_MAX, l0 = 0.0f, l1 = 0.0f;
    float o[5][4];
    #pragma unroll
    for (int nf = 0; nf < 5; nf++)
        #pragma unroll
        for (int r = 0; r < 4; r++) o[nf][r] = 0.0f;

    const int q2 = (lane & 3) * 2;

    for (int t0 = t_start; t0 < t_end; t0 += KTILE) {
        __syncthreads();
        // K tile: 48 rows x 64 cols from d-major global
        for (int i = tid; i < KD * 8; i += 128) {
            int d = i >> 3, seg = i & 7;
            *(uint4*)&Kth[d * SKT + seg * 8] =
                *(const uint4*)&gkh[(size_t)d * NTOK + t0 + seg * 8];
            *(uint4*)&Ktl[d * SKT + seg * 8] =
                *(const uint4*)&gkl[(size_t)d * NTOK + t0 + seg * 8];
        }
        // V tile: 64 rows x 48 cols
        for (int i = tid; i < 64 * 6; i += 128) {
            int j = i / 6, seg = i % 6;
            *(uint4*)&Vh[j * SV + seg * 8] =
                *(const uint4*)&gvh[(size_t)(t0 + j) * KD + seg * 8];
            *(uint4*)&Vl[j * SV + seg * 8] =
                *(const uint4*)&gvl[(size_t)(t0 + j) * KD + seg * 8];
        }
        __syncthreads();

        // ---- S = Q K^T (split bf16) ----
        float c[8][4];
        #pragma unroll
        for (int nf = 0; nf < 8; nf++)
            #pragma unroll
            for (int r = 0; r < 4; r++) c[nf][r] = 0.0f;

        #pragma unroll
        for (int ks = 0; ks < 3; ks++) {
            unsigned ah[4], al[4];
            LDSM_X4(ah[0], ah[1], ah[2], ah[3], aQh + ks * 32);
            LDSM_X4(al[0], al[1], al[2], al[3], aQl + ks * 32);
            #pragma unroll
            for (int nf2 = 0; nf2 < 4; nf2++) {
                unsigned r0, r1, r2, r3;
                unsigned bh0[2], bh1[2], bl0[2], bl1[2];
                LDSM_X4T(r0, r1, r2, r3, aKh + ks * 16 * SKT * 2 + nf2 * 32);
                bh0[0] = r0; bh0[1] = r1; bh1[0] = r2; bh1[1] = r3;
                LDSM_X4T(r0, r1, r2, r3, aKl + ks * 16 * SKT * 2 + nf2 * 32);
                bl0[0] = r0; bl0[1] = r1; bl1[0] = r2; bl1[1] = r3;
                MMA_BF16(c[2 * nf2], ah, bh0);
                MMA_BF16(c[2 * nf2], ah, bl0);
                MMA_BF16(c[2 * nf2], al, bh0);
                MMA_BF16(c[2 * nf2 + 1], ah, bh1);
                MMA_BF16(c[2 * nf2 + 1], ah, bl1);
                MMA_BF16(c[2 * nf2 + 1], al, bh1);
            }
        }

        // ---- softmax (rows r=lane>>2 and r+8) ----
        const int lim = (t_end - t0 < KTILE) ? (t_end - t0) : KTILE;
        float mx0 = -FLT_MAX, mx1 = -FLT_MAX;
        #pragma unroll
        for (int nf = 0; nf < 8; nf++) {
            int col = nf * 8 + q2;
            if (col >= lim)     { c[nf][0] = -FLT_MAX; c[nf][2] = -FLT_MAX; }
            if (col + 1 >= lim) { c[nf][1] = -FLT_MAX; c[nf][3] = -FLT_MAX; }
            mx0 = fmaxf(mx0, fmaxf(c[nf][0], c[nf][1]));
            mx1 = fmaxf(mx1, fmaxf(c[nf][2], c[nf][3]));
        }
        mx0 = fmaxf(mx0, __shfl_xor_sync(0xffffffffu, mx0, 1));
        mx0 = fmaxf(mx0, __shfl_xor_sync(0xffffffffu, mx0, 2));
        mx1 = fmaxf(mx1, __shfl_xor_sync(0xffffffffu, mx1, 1));
        mx1 = fmaxf(mx1, __shfl_xor_sync(0xffffffffu, mx1, 2));

        float mn0 = fmaxf(m0, mx0), mn1 = fmaxf(m1, mx1);
        float cr0 = ex2(m0 - mn0), cr1 = ex2(m1 - mn1);
        m0 = mn0; m1 = mn1;
        l0 *= cr0; l1 *= cr1;
        #pragma unroll
        for (int nf = 0; nf < 5; nf++) {
            o[nf][0] *= cr0; o[nf][1] *= cr0;
            o[nf][2] *= cr1; o[nf][3] *= cr1;
        }

        unsigned phA[8], phB[8], plA[8], plB[8];
        float rs0 = 0.0f, rs1 = 0.0f;
        #pragma unroll
        for (int nf = 0; nf < 8; nf++) {
            float p0 = ex2(c[nf][0] - mn0);
            float p1 = ex2(c[nf][1] - mn0);
            float p2 = ex2(c[nf][2] - mn1);
            float p3 = ex2(c[nf][3] - mn1);
            rs0 += p0 + p1;
            rs1 += p2 + p3;
            float h0 = __bfloat162float(__float2bfloat16_rn(p0));
            float h1 = __bfloat162float(__float2bfloat16_rn(p1));
            float h2 = __bfloat162float(__float2bfloat16_rn(p2));
            float h3 = __bfloat162float(__float2bfloat16_rn(p3));
            phA[nf] = packbf(h0, h1);
            phB[nf] = packbf(h2, h3);
            plA[nf] = packbf(p0 - h0, p1 - h1);
            plB[nf] = packbf(p2 - h2, p3 - h3);
        }
        rs0 += __shfl_xor_sync(0xffffffffu, rs0, 1);
        rs0 += __shfl_xor_sync(0xffffffffu, rs0, 2);
        rs1 += __shfl_xor_sync(0xffffffffu, rs1, 1);
        rs1 += __shfl_xor_sync(0xffffffffu, rs1, 2);
        l0 += rs0; l1 += rs1;

        // ---- O += P V (split bf16) ----
        #pragma unroll
        for (int ks = 0; ks < 4; ks++) {
            unsigned aH[4] = {phA[2 * ks], phB[2 * ks], phA[2 * ks + 1], phB[2 * ks + 1]};
            unsigned aL[4] = {plA[2 * ks], plB[2 * ks], plA[2 * ks + 1], plB[2 * ks + 1]};
            #pragma unroll
            for (int nv2 = 0; nv2 < 2; nv2++) {
                unsigned r0, r1, r2, r3;
                unsigned vh0[2], vh1[2], vl0[2], vl1[2];
                LDSM_X4T(r0, r1, r2, r3, aVh + ks * 16 * SV * 2 + nv2 * 32);
                vh0[0] = r0; vh0[1] = r1; vh1[0] = r2; vh1[1] = r3;
                LDSM_X4T(r0, r1, r2, r3, aVl + ks * 16 * SV * 2 + nv2 * 32);
                vl0[0] = r0; vl0[1] = r1; vl1[0] = r2; vl1[1] = r3;
                MMA_BF16(o[2 * nv2], aH, vh0);
                MMA_BF16(o[2 * nv2], aH, vl0);
                MMA_BF16(o[2 * nv2], aL, vh0);
                MMA_BF16(o[2 * nv2 + 1], aH, vh1);
                MMA_BF16(o[2 * nv2 + 1], aH, vl1);
                MMA_BF16(o[2 * nv2 + 1], aL, vh1);
            }
            {
                unsigned r0, r1, r2, r3;
                unsigned vh0[2], vl0[2];
                LDSM_X4T(r0, r1, r2, r3, aVh + ks * 16 * SV * 2 + 64);
                vh0[0] = r0; vh0[1] = r1;
                LDSM_X4T(r0, r1, r2, r3, aVl + ks * 16 * SV * 2 + 64);
                vl0[0] = r0; vl0[1] = r1;
                MMA_BF16(o[4], aH, vh0);
                MMA_BF16(o[4], aH, vl0);
                MMA_BF16(o[4], aL, vh0);
            }
        }
    }

    // ---- store partials ----
    const int r_local = lane >> 2;
    const int ql0 = qoff + warp * 16 + r_local;
    const int ql1 = ql0 + 8;
    const size_t pb = (size_t)(spl * HEADS + head) * NTOK;
    if ((lane & 3) == 0) {
        if (ql0 < qend) { g_pm[pb + ql0] = m0; g_pl[pb + ql0] = l0; }
        if (ql1 < qend) { g_pm[pb + ql1] = m1; g_pl[pb + ql1] = l1; }
    }
    #pragma unroll
    for (int nf = 0; nf < 5; nf++) {
        int d = nf * 8 + q2;
        if (ql0 < qend)
            *(float2*)&g_pacc[(pb + ql0) * DH + d] = make_float2(o[nf][0], o[nf][1]);
        if (ql1 < qend)
            *(float2*)&g_pacc[(pb + ql1) * DH + d] = make_float2(o[nf][2], o[nf][3]);
    }
}

// ---------------------------------------------------------------------------
// Merge split partials + meanV fill (fused; proven R10 version)
// ---------------------------------------------------------------------------
__global__ __launch_bounds__(256) void reduce_kernel() {
    const int idx = blockIdx.x * 256 + threadIdx.x;
    if (idx >= NTOK * HEADS) return;
    const int ql = idx / HEADS;
    const int head = idx % HEADS;
    const int nq0 = g_grp_cnt[0];
    const int qi = g_qidx[ql];
    float* op = g_o + (size_t)qi * DMODEL + head * DH;

    if (ql < nq0) {
        const float4* mv = (const float4*)(g_meanv + head * DH);
        #pragma unroll
        for (int d4 = 0; d4 < 10; d4++) *(float4*)(op + d4 * 4) = mv[d4];
        return;
    }

    int sig = 1;
    #pragma unroll
    for (int s = 2; s < 8; s++)
        if (ql >= g_grp_off[s]) sig = s;
    const int ns = g_nsplit[sig];

    float m = -FLT_MAX;
    for (int s = 0; s < ns; s++) {
        float ms = g_pm[(size_t)(s * HEADS + head) * NTOK + ql];
        m = fmaxf(m, ms);
    }
    float l = 0.0f;
    for (int s = 0; s < ns; s++) {
        size_t base = (size_t)(s * HEADS + head) * NTOK + ql;
        l += g_pl[base] * ex2(g_pm[base] - m);
    }
    const float inv = 1.0f / l;

    float sum[DH];
    #pragma unroll
    for (int d = 0; d < DH; d++) sum[d] = 0.0f;
    for (int s = 0; s < ns; s++) {
        size_t base = (size_t)(s * HEADS + head) * NTOK + ql;
        float w = ex2(g_pm[base] - m);
        const float4* pa = (const float4*)(g_pacc + base * DH);
        #pragma unroll
        for (int d4 = 0; d4 < 10; d4++) {
            float4 a = pa[d4];
            sum[d4 * 4 + 0] += w * a.x;
            sum[d4 * 4 + 1] += w * a.y;
            sum[d4 * 4 + 2] += w * a.z;
            sum[d4 * 4 + 3] += w * a.w;
        }
    }
    #pragma unroll
    for (int d4 = 0; d4 < 10; d4++) {
        float4 r;
        r.x = sum[d4 * 4 + 0] * inv;
        r.y = sum[d4 * 4 + 1] * inv;
        r.z = sum[d4 * 4 + 2] * inv;
        r.w = sum[d4 * 4 + 3] * inv;
        *(float4*)(op + d4 * 4) = r;
    }
}

// ---------------------------------------------------------------------------
// Output projection via bf16 split MMA (qkv clone + bias epilogue).
// ---------------------------------------------------------------------------
__global__ __launch_bounds__(256) void out_gemm(
    const float* __restrict__ Wo, const float* __restrict__ bo,
    float* __restrict__ out)
{
    __shared__ __nv_bfloat16 Ah[128 * SKA], Al[128 * SKA];
    __shared__ __nv_bfloat16 Bh[32 * SNB],  Bl[32 * SNB];

    const int tid  = threadIdx.x;
    const int lane = tid & 31;
    const int wid  = tid >> 5;
    const int warp_m = wid >> 1;
    const int warp_n = wid & 1;
    const int m0 = blockIdx.y * 128;
    const int n0 = blockIdx.x * 64;
    const int quad = lane >> 3, rr = lane & 7;

    float c[2][4][4];
    #pragma unroll
    for (int mf = 0; mf < 2; mf++)
        #pragma unroll
        for (int nf = 0; nf < 4; nf++)
            #pragma unroll
            for (int r = 0; r < 4; r++) c[mf][nf][r] = 0.0f;

    const int arow = tid >> 1, ahalf = (tid & 1) * 16;
    const int brow = tid >> 3, bcol = (tid & 7) * 8;

    unsigned aAh[2], aAl[2];
    #pragma unroll
    for (int mf = 0; mf < 2; mf++) {
        int mrow = warp_m * 32 + mf * 16 + (quad & 1) * 8 + rr;
        int kcol = (quad >> 1) * 8;
        aAh[mf] = s2u(&Ah[mrow * SKA + kcol]);
        aAl[mf] = s2u(&Al[mrow * SKA + kcol]);
    }
    unsigned aBh[2], aBl[2];
    #pragma unroll
    for (int nf2 = 0; nf2 < 2; nf2++) {
        int krow = (quad & 1) * 8 + rr;
        int ncol = warp_n * 32 + nf2 * 16 + (quad >> 1) * 8;
        aBh[nf2] = s2u(&Bh[krow * SNB + ncol]);
        aBl[nf2] = s2u(&Bl[krow * SNB + ncol]);
    }

    for (int k0 = 0; k0 < DMODEL; k0 += 32) {
        float4 av[4], wv[2];
        const float4* asrc = (const float4*)(g_o + (size_t)(m0 + arow) * DMODEL + k0 + ahalf);
        #pragma unroll
        for (int j = 0; j < 4; j++) av[j] = asrc[j];
        const float4* wsrc = (const float4*)(Wo + (size_t)(k0 + brow) * DMODEL + n0 + bcol);
        #pragma unroll
        for (int j = 0; j < 2; j++) wv[j] = wsrc[j];
        __syncthreads();

        #pragma unroll
        for (int j = 0; j < 4; j++) {
            float f[4] = {av[j].x, av[j].y, av[j].z, av[j].w};
            #pragma unroll
            for (int e = 0; e < 4; e += 2) {
                __nv_bfloat16 h0 = __float2bfloat16_rn(f[e]);
                __nv_bfloat16 h1 = __float2bfloat16_rn(f[e + 1]);
                __nv_bfloat16 l0 = __float2bfloat16_rn(f[e] - __bfloat162float(h0));
                __nv_bfloat16 l1 = __float2bfloat16_rn(f[e + 1] - __bfloat162float(h1));
                int off = arow * SKA + ahalf + j * 4 + e;
                *(__nv_bfloat162*)&Ah[off] = __nv_bfloat162(h0, h1);
                *(__nv_bfloat162*)&Al[off] = __nv_bfloat162(l0, l1);
            }
        }
        #pragma unroll
        for (int j = 0; j < 2; j++) {
            float f[4] = {wv[j].x, wv[j].y, wv[j].z, wv[j].w};
            #pragma unroll
            for (int e = 0; e < 4; e += 2) {
                __nv_bfloat16 h0 = __float2bfloat16_rn(f[e]);
                __nv_bfloat16 h1 = __float2bfloat16_rn(f[e + 1]);
                __nv_bfloat16 l0 = __float2bfloat16_rn(f[e] - __bfloat162float(h0));
                __nv_bfloat16 l1 = __float2bfloat16_rn(f[e + 1] - __bfloat162float(h1));
                int off = brow * SNB + bcol + j * 4 + e;
                *(__nv_bfloat162*)&Bh[off] = __nv_bfloat162(h0, h1);
                *(__nv_bfloat162*)&Bl[off] = __nv_bfloat162(l0, l1);
            }
        }
        __syncthreads();

        #pragma unroll
        for (int ks = 0; ks < 2; ks++) {
            const unsigned koffA = ks * 16 * 2;
            const unsigned koffB = (unsigned)(ks * 16 * SNB * 2);
            unsigned ah[2][4], al[2][4];
            #pragma unroll
            for (int mf = 0; mf < 2; mf++) {
                LDSM_X4(ah[mf][0], ah[mf][1], ah[mf][2], ah[mf][3], aAh[mf] + koffA);
                LDSM_X4(al[mf][0], al[mf][1], al[mf][2], al[mf][3], aAl[mf] + koffA);
            }
            unsigned bh[4][2], bl[4][2];
            #pragma unroll
            for (int nf2 = 0; nf2 < 2; nf2++) {
                unsigned r0, r1, r2, r3;
                LDSM_X4T(r0, r1, r2, r3, aBh[nf2] + koffB);
                bh[nf2 * 2][0] = r0;  bh[nf2 * 2][1] = r1;
                bh[nf2 * 2 + 1][0] = r2;  bh[nf2 * 2 + 1][1] = r3;
                LDSM_X4T(r0, r1, r2, r3, aBl[nf2] + koffB);
                bl[nf2 * 2][0] = r0;  bl[nf2 * 2][1] = r1;
                bl[nf2 * 2 + 1][0] = r2;  bl[nf2 * 2 + 1][1] = r3;
            }
            #pragma unroll
            for (int mf = 0; mf < 2; mf++)
                #pragma unroll
                for (int nf = 0; nf < 4; nf++) {
                    MMA_BF16(c[mf][nf], ah[mf], bh[nf]);
                    MMA_BF16(c[mf][nf], ah[mf], bl[nf]);
                    MMA_BF16(c[mf][nf], al[mf], bh[nf]);
                }
        }
    }

    #pragma unroll
    for (int mf = 0; mf < 2; mf++) {
        #pragma unroll
        for (int nf = 0; nf < 4; nf++) {
            int row = m0 + warp_m * 32 + mf * 16 + (lane >> 2);
            int col = n0 + warp_n * 32 + nf * 8 + (lane & 3) * 2;
            float2 b = *(const float2*)(bo + col);
            *(float2*)&out[(size_t)row * DMODEL + col] =
                make_float2(c[mf][nf][0] + b.x, c[mf][nf][1] + b.y);
            *(float2*)&out[(size_t)(row + 8) * DMODEL + col] =
                make_float2(c[mf][nf][2] + b.x, c[mf][nf][3] + b.y);
        }
    }
}

// ---------------------------------------------------------------------------
extern "C" void kernel_launch(void* const* d_in, const int* in_sizes, int n_in,
                              void* d_out, int out_size)
{
    const float* x  = (const float*)d_in[0];
    const float* gm = (const float*)d_in[1];
    const float* Wq = (const float*)d_in[2];
    const float* Wk = (const float*)d_in[3];
    const float* Wv = (const float*)d_in[4];
    const float* Wo = (const float*)d_in[5];
    const float* bo = (const float*)d_in[6];
    float* out = (float*)d_out;

    plan_kernel<<<1, 256>>>(gm);

    dim3 gq(DMODEL / 64, NTOK / 128, 3);
    qkv_gemm<<<gq, 256>>>(x, Wq, Wk, Wv);

    dim3 gg(NTOK / 128, 7, HEADS);
    gather_kernel<<<gg, 128>>>();

    dim3 gm1(HEADS, 16);
    meanv1_kernel<<<gm1, 320>>>();
    meanv2_kernel<<<1, 320>>>();

    dim3 ga(MAXU, HEADS);
    attn_kernel<<<ga, 128>>>();

    reduce_kernel<<<(NTOK * HEADS + 255) / 256, 256>>>();

    dim3 go(DMODEL / 64, NTOK / 128);
    out_gemm<<<go, 256>>>(Wo, bo, out);
}

// round 12
// speedup vs baseline: 1.6127x; 1.6127x over previous
#include <cuda_runtime.h>
#include <cuda_bf16.h>
#include <float.h>

#define NTOK   4096
#define DMODEL 320
#define HEADS  8
#define DH     40
#define NPHASE 3
#define KTILE  64
#define QBLK   64
#define UT     4
#define MAXU   1152
#define MAXSPL 16

typedef unsigned long long ull;

#define FMA2(d, a, b, c) \
    asm("fma.rn.f32x2 %0, %1, %2, %3;" : "=l"(d) : "l"(a), "l"(b), "l"(c))
#define MUL2(d, a, b) \
    asm("mul.rn.f32x2 %0, %1, %2;" : "=l"(d) : "l"(a), "l"(b))
#define PACK2(d, lo, hi) \
    asm("mov.b64 %0, {%1, %2};" : "=l"(d) : "f"(lo), "f"(hi))
#define UNPACK2(lo, hi, v) \
    asm("mov.b64 {%0, %1}, %2;" : "=f"(lo), "=f"(hi) : "l"(v))

#define LDSM_X4(r0, r1, r2, r3, addr) \
    asm volatile("ldmatrix.sync.aligned.m8n8.x4.shared.b16 {%0,%1,%2,%3}, [%4];" \
        : "=r"(r0), "=r"(r1), "=r"(r2), "=r"(r3) : "r"(addr))
#define LDSM_X4T(r0, r1, r2, r3, addr) \
    asm volatile("ldmatrix.sync.aligned.m8n8.x4.trans.shared.b16 {%0,%1,%2,%3}, [%4];" \
        : "=r"(r0), "=r"(r1), "=r"(r2), "=r"(r3) : "r"(addr))
#define MMA_BF16(c, a, b) \
    asm volatile("mma.sync.aligned.m16n8k16.row.col.f32.bf16.bf16.f32 " \
        "{%0,%1,%2,%3}, {%4,%5,%6,%7}, {%8,%9}, {%0,%1,%2,%3};" \
        : "+f"((c)[0]), "+f"((c)[1]), "+f"((c)[2]), "+f"((c)[3]) \
        : "r"((a)[0]), "r"((a)[1]), "r"((a)[2]), "r"((a)[3]), \
          "r"((b)[0]), "r"((b)[1]))

// ---------------- scratch (__device__ globals; no allocation allowed) -------
__device__ float g_q[HEADS * NTOK * DH];
__device__ float g_k[HEADS * NTOK * DH];
__device__ float g_v[HEADS * NTOK * DH];
__device__ float g_o[NTOK * DMODEL];

// planning data
__device__ int g_grp_cnt[8], g_grp_off[8];
__device__ int g_qidx[NTOK];
__device__ int g_kcnt[8];
__device__ int g_kidx[8][NTOK];
__device__ int g_nsplit[8];
__device__ int g_u_sig[MAXU], g_u_qoff[MAXU], g_u_qend[MAXU];
__device__ int g_u_t0[MAXU], g_u_t1[MAXU], g_u_spl[MAXU];
__device__ int g_nunits;

// compacted K/V: [sig-1][head][jc][40]
__device__ float g_kc[7 * HEADS * NTOK * DH];
__device__ float g_vc[7 * HEADS * NTOK * DH];
__device__ float g_meanv[HEADS * DH];
__device__ float g_mvpart[16][HEADS * DH];

// split partials: indexed [spl][head][ql]
__device__ float g_pacc[MAXSPL * HEADS * NTOK * DH];
__device__ float g_pm[MAXSPL * HEADS * NTOK];
__device__ float g_pl[MAXSPL * HEADS * NTOK];

__device__ __forceinline__ float ex2(float x) {
    float r;
    asm("ex2.approx.ftz.f32 %0, %1;" : "=f"(r) : "f"(x));
    return r;
}
__device__ __forceinline__ unsigned s2u(const void* p) {
    return (unsigned)__cvta_generic_to_shared(p);
}

// ---------------------------------------------------------------------------
// Plan kernel (mask packing fused; proven R10 version)
// ---------------------------------------------------------------------------
__global__ __launch_bounds__(256) void plan_kernel(const float* __restrict__ gm) {
    __shared__ unsigned smb[NPHASE * (NTOK / 32)];
    __shared__ int sq[8][256];
    __shared__ int sk[8][256];
    __shared__ int base_q[8];
    const int t = threadIdx.x;

    {
        unsigned bits = 0;
        #pragma unroll 8
        for (int b = 0; b < 32; b++)
            if (gm[t * 32 + b] != 0.0f) bits |= (1u << b);
        smb[t] = bits;
        if (t < 128) {
            unsigned bits2 = 0;
            #pragma unroll 8
            for (int b = 0; b < 32; b++)
                if (gm[(256 + t) * 32 + b] != 0.0f) bits2 |= (1u << b);
            smb[256 + t] = bits2;
        }
    }
    __syncthreads();

    unsigned bits_arr[16];
    int cq[8], ck[8];
    #pragma unroll
    for (int s = 0; s < 8; s++) { cq[s] = 0; ck[s] = 0; }

    for (int u = 0; u < 16; u++) {
        int i = t * 16 + u;
        unsigned b = 0;
        #pragma unroll
        for (int p = 0; p < NPHASE; p++)
            b |= ((smb[p * 128 + (i >> 5)] >> (i & 31)) & 1u) << p;
        bits_arr[u] = b;
        cq[b]++;
        #pragma unroll
        for (int s = 1; s < 8; s++)
            if (b & (unsigned)s) ck[s]++;
    }
    #pragma unroll
    for (int s = 0; s < 8; s++) { sq[s][t] = cq[s]; sk[s][t] = ck[s]; }
    __syncthreads();

    for (int g = 0; g < 15; g++) {
        int* arr = (g < 8) ? sq[g] : sk[g - 7];
        for (int off = 1; off < 256; off <<= 1) {
            int u = (t >= off) ? arr[t - off] : 0;
            __syncthreads();
            arr[t] += u;
            __syncthreads();
        }
    }

    if (t == 0) {
        int acc = 0;
        for (int s = 0; s < 8; s++) {
            base_q[s] = acc;
            g_grp_off[s] = acc;
            int tot = sq[s][255];
            g_grp_cnt[s] = tot;
            acc += tot;
        }
        int nu = 0;
        for (int s = 1; s < 8; s++) {
            int kc = sk[s][255];
            g_kcnt[s] = kc;
            int cnt = sq[s][255], off = base_q[s];
            int tiles = (kc + KTILE - 1) / KTILE;
            int ns = (tiles + UT - 1) / UT;
            g_nsplit[s] = ns;
            for (int b = 0; b * QBLK < cnt; b++) {
                for (int sp = 0; sp < ns; sp++) {
                    g_u_sig[nu] = s;
                    g_u_qoff[nu] = off + b * QBLK;
                    g_u_qend[nu] = off + cnt;
                    g_u_t0[nu] = sp * UT * KTILE;
                    int t1 = (sp + 1) * UT * KTILE;
                    g_u_t1[nu] = (t1 < kc) ? t1 : kc;
                    g_u_spl[nu] = sp;
                    nu++;
                }
            }
        }
        g_nunits = nu;
    }
    __syncthreads();

    int qcur[8], kcur[8];
    #pragma unroll
    for (int s = 0; s < 8; s++) {
        qcur[s] = base_q[s] + sq[s][t] - cq[s];
        kcur[s] = sk[s][t] - ck[s];
    }
    for (int u = 0; u < 16; u++) {
        int i = t * 16 + u;
        unsigned b = bits_arr[u];
        g_qidx[qcur[b]++] = i;
        #pragma unroll
        for (int s = 1; s < 8; s++)
            if (b & (unsigned)s) g_kidx[s][kcur[s]++] = i;
    }
}

// ---------------------------------------------------------------------------
// QKV projection via bf16 split-precision MMA (proven R10 version).
// ---------------------------------------------------------------------------
#define SKA 40
#define SNB 72

__global__ __launch_bounds__(256) void qkv_gemm(
    const float* __restrict__ X,
    const float* __restrict__ Wq, const float* __restrict__ Wk,
    const float* __restrict__ Wv)
{
    const float* W = (blockIdx.z == 0) ? Wq : (blockIdx.z == 1) ? Wk : Wv;
    float* Dst = (blockIdx.z == 0) ? g_q : (blockIdx.z == 1) ? g_k : g_v;

    __shared__ __nv_bfloat16 Ah[128 * SKA], Al[128 * SKA];
    __shared__ __nv_bfloat16 Bh[32 * SNB],  Bl[32 * SNB];

    const int tid  = threadIdx.x;
    const int lane = tid & 31;
    const int wid  = tid >> 5;
    const int warp_m = wid >> 1;
    const int warp_n = wid & 1;
    const int m0 = blockIdx.y * 128;
    const int n0 = blockIdx.x * 64;
    const int quad = lane >> 3, rr = lane & 7;

    float c[2][4][4];
    #pragma unroll
    for (int mf = 0; mf < 2; mf++)
        #pragma unroll
        for (int nf = 0; nf < 4; nf++)
            #pragma unroll
            for (int r = 0; r < 4; r++) c[mf][nf][r] = 0.0f;

    const int arow = tid >> 1, ahalf = (tid & 1) * 16;
    const int brow = tid >> 3, bcol = (tid & 7) * 8;

    unsigned aAh[2], aAl[2];
    #pragma unroll
    for (int mf = 0; mf < 2; mf++) {
        int mrow = warp_m * 32 + mf * 16 + (quad & 1) * 8 + rr;
        int kcol = (quad >> 1) * 8;
        aAh[mf] = s2u(&Ah[mrow * SKA + kcol]);
        aAl[mf] = s2u(&Al[mrow * SKA + kcol]);
    }
    unsigned aBh[2], aBl[2];
    #pragma unroll
    for (int nf2 = 0; nf2 < 2; nf2++) {
        int krow = (quad & 1) * 8 + rr;
        int ncol = warp_n * 32 + nf2 * 16 + (quad >> 1) * 8;
        aBh[nf2] = s2u(&Bh[krow * SNB + ncol]);
        aBl[nf2] = s2u(&Bl[krow * SNB + ncol]);
    }

    for (int k0 = 0; k0 < DMODEL; k0 += 32) {
        float4 av[4], wv[2];
        const float4* asrc = (const float4*)(X + (size_t)(m0 + arow) * DMODEL + k0 + ahalf);
        #pragma unroll
        for (int j = 0; j < 4; j++) av[j] = asrc[j];
        const float4* wsrc = (const float4*)(W + (size_t)(k0 + brow) * DMODEL + n0 + bcol);
        #pragma unroll
        for (int j = 0; j < 2; j++) wv[j] = wsrc[j];
        __syncthreads();

        #pragma unroll
        for (int j = 0; j < 4; j++) {
            float f[4] = {av[j].x, av[j].y, av[j].z, av[j].w};
            #pragma unroll
            for (int e = 0; e < 4; e += 2) {
                __nv_bfloat16 h0 = __float2bfloat16_rn(f[e]);
                __nv_bfloat16 h1 = __float2bfloat16_rn(f[e + 1]);
                __nv_bfloat16 l0 = __float2bfloat16_rn(f[e] - __bfloat162float(h0));
                __nv_bfloat16 l1 = __float2bfloat16_rn(f[e + 1] - __bfloat162float(h1));
                int off = arow * SKA + ahalf + j * 4 + e;
                *(__nv_bfloat162*)&Ah[off] = __nv_bfloat162(h0, h1);
                *(__nv_bfloat162*)&Al[off] = __nv_bfloat162(l0, l1);
            }
        }
        #pragma unroll
        for (int j = 0; j < 2; j++) {
            float f[4] = {wv[j].x, wv[j].y, wv[j].z, wv[j].w};
            #pragma unroll
            for (int e = 0; e < 4; e += 2) {
                __nv_bfloat16 h0 = __float2bfloat16_rn(f[e]);
                __nv_bfloat16 h1 = __float2bfloat16_rn(f[e + 1]);
                __nv_bfloat16 l0 = __float2bfloat16_rn(f[e] - __bfloat162float(h0));
                __nv_bfloat16 l1 = __float2bfloat16_rn(f[e + 1] - __bfloat162float(h1));
                int off = brow * SNB + bcol + j * 4 + e;
                *(__nv_bfloat162*)&Bh[off] = __nv_bfloat162(h0, h1);
                *(__nv_bfloat162*)&Bl[off] = __nv_bfloat162(l0, l1);
            }
        }
        __syncthreads();

        #pragma unroll
        for (int ks = 0; ks < 2; ks++) {
            const unsigned koffA = ks * 16 * 2;
            const unsigned koffB = (unsigned)(ks * 16 * SNB * 2);
            unsigned ah[2][4], al[2][4];
            #pragma unroll
            for (int mf = 0; mf < 2; mf++) {
                LDSM_X4(ah[mf][0], ah[mf][1], ah[mf][2], ah[mf][3], aAh[mf] + koffA);
                LDSM_X4(al[mf][0], al[mf][1], al[mf][2], al[mf][3], aAl[mf] + koffA);
            }
            unsigned bh[4][2], bl[4][2];
            #pragma unroll
            for (int nf2 = 0; nf2 < 2; nf2++) {
                unsigned r0, r1, r2, r3;
                LDSM_X4T(r0, r1, r2, r3, aBh[nf2] + koffB);
                bh[nf2 * 2][0] = r0;  bh[nf2 * 2][1] = r1;
                bh[nf2 * 2 + 1][0] = r2;  bh[nf2 * 2 + 1][1] = r3;
                LDSM_X4T(r0, r1, r2, r3, aBl[nf2] + koffB);
                bl[nf2 * 2][0] = r0;  bl[nf2 * 2][1] = r1;
                bl[nf2 * 2 + 1][0] = r2;  bl[nf2 * 2 + 1][1] = r3;
            }
            #pragma unroll
            for (int mf = 0; mf < 2; mf++)
                #pragma unroll
                for (int nf = 0; nf < 4; nf++) {
                    MMA_BF16(c[mf][nf], ah[mf], bh[nf]);
                    MMA_BF16(c[mf][nf], ah[mf], bl[nf]);
                    MMA_BF16(c[mf][nf], al[mf], bh[nf]);
                }
        }
    }

    #pragma unroll
    for (int mf = 0; mf < 2; mf++) {
        #pragma unroll
        for (int nf = 0; nf < 4; nf++) {
            int row = m0 + warp_m * 32 + mf * 16 + (lane >> 2);
            int col = n0 + warp_n * 32 + nf * 8 + (lane & 3) * 2;
            int h = col / DH, d = col % DH;
            float* base = Dst + (size_t)h * NTOK * DH;
            *(float2*)&base[(size_t)row * DH + d] =
                make_float2(c[mf][nf][0], c[mf][nf][1]);
            *(float2*)&base[(size_t)(row + 8) * DH + d] =
                make_float2(c[mf][nf][2], c[mf][nf][3]);
        }
    }
}

// ---------------------------------------------------------------------------
// Gather compacted fp32 K/V; zero-pad (proven R10 version).
// ---------------------------------------------------------------------------
__global__ __launch_bounds__(320) void gather_kernel() {
    const int sig = blockIdx.y + 1;
    const int head = blockIdx.z;
    const int kc = g_kcnt[sig];
    const int pad = (kc + KTILE - 1) & ~(KTILE - 1);
    const int jc = blockIdx.x * 32 + threadIdx.x / 10;
    const int c4 = threadIdx.x % 10;
    if (jc >= pad) return;

    size_t dst = ((size_t)((sig - 1) * HEADS + head) * NTOK + jc) * DH + c4 * 4;
    float4 kv = make_float4(0.f, 0.f, 0.f, 0.f);
    float4 vv = make_float4(0.f, 0.f, 0.f, 0.f);
    if (jc < kc) {
        int j = g_kidx[sig][jc];
        size_t src = ((size_t)head * NTOK + j) * DH + c4 * 4;
        kv = *(const float4*)(g_k + src);
        vv = *(const float4*)(g_v + src);
    }
    *(float4*)(g_kc + dst) = kv;
    *(float4*)(g_vc + dst) = vv;
}

// ---------------------------------------------------------------------------
// Per-head V column mean: two-stage (proven R11 version)
// ---------------------------------------------------------------------------
__global__ __launch_bounds__(320) void meanv1_kernel() {
    __shared__ float red[320];
    const int head = blockIdx.x;
    const int chunk = blockIdx.y;
    const int t = threadIdx.x;
    const int d = t % DH, r = t / DH;
    float s = 0.0f;
    const int j0 = chunk * 256;
    for (int j = j0 + r; j < j0 + 256; j += 8)
        s += g_v[((size_t)head * NTOK + j) * DH + d];
    red[t] = s;
    __syncthreads();
    if (r == 0) {
        float tot = 0.0f;
        #pragma unroll
        for (int rr = 0; rr < 8; rr++) tot += red[rr * DH + d];
        g_mvpart[chunk][head * DH + d] = tot;
    }
}

__global__ __launch_bounds__(320) void meanv2_kernel() {
    const int i = threadIdx.x;
    float s = 0.0f;
    #pragma unroll
    for (int c = 0; c < 16; c++) s += g_mvpart[c][i];
    g_meanv[i] = s * (1.0f / (float)NTOK);
}

// ---------------------------------------------------------------------------
// Flash attention over uniform work units (proven R9/R10 scalar version).
// 128 threads = 64 queries x 2 dim-halves; f32x2 math, log2 softmax.
// ---------------------------------------------------------------------------
__global__ __launch_bounds__(128) void attn_kernel() {
    if (blockIdx.x >= g_nunits) return;
    __shared__ __align__(16) float ksh[KTILE * DH];
    __shared__ __align__(16) float vsh[KTILE * DH];

    const int tid  = threadIdx.x;
    const int head = blockIdx.y;
    const int uix  = blockIdx.x;
    const int sig  = g_u_sig[uix];
    const int qoff = g_u_qoff[uix];
    const int qend = g_u_qend[uix];
    const int t_start = g_u_t0[uix];
    const int t_end   = g_u_t1[uix];
    const int spl  = g_u_spl[uix];
    const int q    = tid >> 1;
    const int half = tid & 1;
    const int ql   = qoff + q;
    const bool vq  = ql < qend;
    const int qi   = g_qidx[vq ? ql : qoff];
    const float scale = 0.15811388300841898f * 1.4426950408889634f;

    const float* Kb = g_kc + (size_t)((sig - 1) * HEADS + head) * NTOK * DH;
    const float* Vb = g_vc + (size_t)((sig - 1) * HEADS + head) * NTOK * DH;

    ull q2[10];
    {
        const float4* qp = (const float4*)(g_q + ((size_t)head * NTOK + qi) * DH + half * 20);
        #pragma unroll
        for (int i = 0; i < 5; i++) {
            float4 v = qp[i];
            PACK2(q2[2 * i + 0], v.x * scale, v.y * scale);
            PACK2(q2[2 * i + 1], v.z * scale, v.w * scale);
        }
    }

    float m = -FLT_MAX, l = 0.0f;
    ull acc2[10];
    #pragma unroll
    for (int d = 0; d < 10; d++) acc2[d] = 0ull;

    for (int t0 = t_start; t0 < t_end; t0 += KTILE) {
        __syncthreads();
        const float4* kg = (const float4*)(Kb + (size_t)t0 * DH);
        const float4* vg = (const float4*)(Vb + (size_t)t0 * DH);
        float4* ks4 = (float4*)ksh;
        float4* vs4 = (float4*)vsh;
        #pragma unroll
        for (int i = tid; i < KTILE * DH / 4; i += 128) {
            ks4[i] = kg[i];
            vs4[i] = vg[i];
        }
        __syncthreads();

        const int lim = (t_end - t0 < KTILE) ? (t_end - t0) : KTILE;
        for (int c = 0; c < lim; c += 16) {
            float s[16];
            float cmax = -FLT_MAX;
            #pragma unroll
            for (int j = 0; j < 16; j++) {
                const ulonglong2* kr =
                    (const ulonglong2*)(ksh + (c + j) * DH + half * 20);
                ull sva = 0ull, svb = 0ull;
                ulonglong2 k0 = kr[0], k1 = kr[1], k2 = kr[2], k3 = kr[3], k4 = kr[4];
                FMA2(sva, q2[0], k0.x, sva);
                FMA2(svb, q2[1], k0.y, svb);
                FMA2(sva, q2[2], k1.x, sva);
                FMA2(svb, q2[3], k1.y, svb);
                FMA2(sva, q2[4], k2.x, sva);
                FMA2(svb, q2[5], k2.y, svb);
                FMA2(sva, q2[6], k3.x, sva);
                FMA2(svb, q2[7], k3.y, svb);
                FMA2(sva, q2[8], k4.x, sva);
                FMA2(svb, q2[9], k4.y, svb);
                float la, ha, lb, hb;
                UNPACK2(la, ha, sva);
                UNPACK2(lb, hb, svb);
                float svf = (la + ha) + (lb + hb);
                svf += __shfl_xor_sync(0xffffffffu, svf, 1);
                s[j] = (c + j < lim) ? svf : -FLT_MAX;
                cmax = fmaxf(cmax, s[j]);
            }
            float mnew = fmaxf(m, cmax);
            float corr = ex2(m - mnew);
            l *= corr;
            {
                ull corr2;
                PACK2(corr2, corr, corr);
                #pragma unroll
                for (int d = 0; d < 10; d++) MUL2(acc2[d], acc2[d], corr2);
            }
            #pragma unroll
            for (int j = 0; j < 16; j++) {
                float pj = ex2(s[j] - mnew);
                l += pj;
                ull pj2;
                PACK2(pj2, pj, pj);
                const ulonglong2* vr =
                    (const ulonglong2*)(vsh + (c + j) * DH + half * 20);
                ulonglong2 v0 = vr[0], v1 = vr[1], v2 = vr[2], v3 = vr[3], v4 = vr[4];
                FMA2(acc2[0], pj2, v0.x, acc2[0]);
                FMA2(acc2[1], pj2, v0.y, acc2[1]);
                FMA2(acc2[2], pj2, v1.x, acc2[2]);
                FMA2(acc2[3], pj2, v1.y, acc2[3]);
                FMA2(acc2[4], pj2, v2.x, acc2[4]);
                FMA2(acc2[5], pj2, v2.y, acc2[5]);
                FMA2(acc2[6], pj2, v3.x, acc2[6]);
                FMA2(acc2[7], pj2, v3.y, acc2[7]);
                FMA2(acc2[8], pj2, v4.x, acc2[8]);
                FMA2(acc2[9], pj2, v4.y, acc2[9]);
            }
            m = mnew;
        }
    }

    if (vq) {
        size_t base = (size_t)(spl * HEADS + head) * NTOK + ql;
        if (half == 0) {
            g_pm[base] = m;
            g_pl[base] = l;
        }
        float4* pp = (float4*)(g_pacc + base * DH + half * 20);
        #pragma unroll
        for (int d4 = 0; d4 < 5; d4++) {
            float4 r;
            UNPACK2(r.x, r.y, acc2[2 * d4 + 0]);
            UNPACK2(r.z, r.w, acc2[2 * d4 + 1]);
            pp[d4] = r;
        }
    }
}

// ---------------------------------------------------------------------------
// Merge split partials + meanV fill (fused; proven R10 version)
// ---------------------------------------------------------------------------
__global__ __launch_bounds__(256) void reduce_kernel() {
    const int idx = blockIdx.x * 256 + threadIdx.x;
    if (idx >= NTOK * HEADS) return;
    const int ql = idx / HEADS;
    const int head = idx % HEADS;
    const int nq0 = g_grp_cnt[0];
    const int qi = g_qidx[ql];
    float* op = g_o + (size_t)qi * DMODEL + head * DH;

    if (ql < nq0) {
        const float4* mv = (const float4*)(g_meanv + head * DH);
        #pragma unroll
        for (int d4 = 0; d4 < 10; d4++) *(float4*)(op + d4 * 4) = mv[d4];
        return;
    }

    int sig = 1;
    #pragma unroll
    for (int s = 2; s < 8; s++)
        if (ql >= g_grp_off[s]) sig = s;
    const int ns = g_nsplit[sig];

    float m = -FLT_MAX;
    for (int s = 0; s < ns; s++) {
        float ms = g_pm[(size_t)(s * HEADS + head) * NTOK + ql];
        m = fmaxf(m, ms);
    }
    float l = 0.0f;
    for (int s = 0; s < ns; s++) {
        size_t base = (size_t)(s * HEADS + head) * NTOK + ql;
        l += g_pl[base] * ex2(g_pm[base] - m);
    }
    const float inv = 1.0f / l;

    float sum[DH];
    #pragma unroll
    for (int d = 0; d < DH; d++) sum[d] = 0.0f;
    for (int s = 0; s < ns; s++) {
        size_t base = (size_t)(s * HEADS + head) * NTOK + ql;
        float w = ex2(g_pm[base] - m);
        const float4* pa = (const float4*)(g_pacc + base * DH);
        #pragma unroll
        for (int d4 = 0; d4 < 10; d4++) {
            float4 a = pa[d4];
            sum[d4 * 4 + 0] += w * a.x;
            sum[d4 * 4 + 1] += w * a.y;
            sum[d4 * 4 + 2] += w * a.z;
            sum[d4 * 4 + 3] += w * a.w;
        }
    }
    #pragma unroll
    for (int d4 = 0; d4 < 10; d4++) {
        float4 r;
        r.x = sum[d4 * 4 + 0] * inv;
        r.y = sum[d4 * 4 + 1] * inv;
        r.z = sum[d4 * 4 + 2] * inv;
        r.w = sum[d4 * 4 + 3] * inv;
        *(float4*)(op + d4 * 4) = r;
    }
}

// ---------------------------------------------------------------------------
// Output projection via bf16 split MMA (proven R11 version).
// ---------------------------------------------------------------------------
__global__ __launch_bounds__(256) void out_gemm(
    const float* __restrict__ Wo, const float* __restrict__ bo,
    float* __restrict__ out)
{
    __shared__ __nv_bfloat16 Ah[128 * SKA], Al[128 * SKA];
    __shared__ __nv_bfloat16 Bh[32 * SNB],  Bl[32 * SNB];

    const int tid  = threadIdx.x;
    const int lane = tid & 31;
    const int wid  = tid >> 5;
    const int warp_m = wid >> 1;
    const int warp_n = wid & 1;
    const int m0 = blockIdx.y * 128;
    const int n0 = blockIdx.x * 64;
    const int quad = lane >> 3, rr = lane & 7;

    float c[2][4][4];
    #pragma unroll
    for (int mf = 0; mf < 2; mf++)
        #pragma unroll
        for (int nf = 0; nf < 4; nf++)
            #pragma unroll
            for (int r = 0; r < 4; r++) c[mf][nf][r] = 0.0f;

    const int arow = tid >> 1, ahalf = (tid & 1) * 16;
    const int brow = tid >> 3, bcol = (tid & 7) * 8;

    unsigned aAh[2], aAl[2];
    #pragma unroll
    for (int mf = 0; mf < 2; mf++) {
        int mrow = warp_m * 32 + mf * 16 + (quad & 1) * 8 + rr;
        int kcol = (quad >> 1) * 8;
        aAh[mf] = s2u(&Ah[mrow * SKA + kcol]);
        aAl[mf] = s2u(&Al[mrow * SKA + kcol]);
    }
    unsigned aBh[2], aBl[2];
    #pragma unroll
    for (int nf2 = 0; nf2 < 2; nf2++) {
        int krow = (quad & 1) * 8 + rr;
        int ncol = warp_n * 32 + nf2 * 16 + (quad >> 1) * 8;
        aBh[nf2] = s2u(&Bh[krow * SNB + ncol]);
        aBl[nf2] = s2u(&Bl[krow * SNB + ncol]);
    }

    for (int k0 = 0; k0 < DMODEL; k0 += 32) {
        float4 av[4], wv[2];
        const float4* asrc = (const float4*)(g_o + (size_t)(m0 + arow) * DMODEL + k0 + ahalf);
        #pragma unroll
        for (int j = 0; j < 4; j++) av[j] = asrc[j];
        const float4* wsrc = (const float4*)(Wo + (size_t)(k0 + brow) * DMODEL + n0 + bcol);
        #pragma unroll
        for (int j = 0; j < 2; j++) wv[j] = wsrc[j];
        __syncthreads();

        #pragma unroll
        for (int j = 0; j < 4; j++) {
            float f[4] = {av[j].x, av[j].y, av[j].z, av[j].w};
            #pragma unroll
            for (int e = 0; e < 4; e += 2) {
                __nv_bfloat16 h0 = __float2bfloat16_rn(f[e]);
                __nv_bfloat16 h1 = __float2bfloat16_rn(f[e + 1]);
                __nv_bfloat16 l0 = __float2bfloat16_rn(f[e] - __bfloat162float(h0));
                __nv_bfloat16 l1 = __float2bfloat16_rn(f[e + 1] - __bfloat162float(h1));
                int off = arow * SKA + ahalf + j * 4 + e;
                *(__nv_bfloat162*)&Ah[off] = __nv_bfloat162(h0, h1);
                *(__nv_bfloat162*)&Al[off] = __nv_bfloat162(l0, l1);
            }
        }
        #pragma unroll
        for (int j = 0; j < 2; j++) {
            float f[4] = {wv[j].x, wv[j].y, wv[j].z, wv[j].w};
            #pragma unroll
            for (int e = 0; e < 4; e += 2) {
                __nv_bfloat16 h0 = __float2bfloat16_rn(f[e]);
                __nv_bfloat16 h1 = __float2bfloat16_rn(f[e + 1]);
                __nv_bfloat16 l0 = __float2bfloat16_rn(f[e] - __bfloat162float(h0));
                __nv_bfloat16 l1 = __float2bfloat16_rn(f[e + 1] - __bfloat162float(h1));
                int off = brow * SNB + bcol + j * 4 + e;
                *(__nv_bfloat162*)&Bh[off] = __nv_bfloat162(h0, h1);
                *(__nv_bfloat162*)&Bl[off] = __nv_bfloat162(l0, l1);
            }
        }
        __syncthreads();

        #pragma unroll
        for (int ks = 0; ks < 2; ks++) {
            const unsigned koffA = ks * 16 * 2;
            const unsigned koffB = (unsigned)(ks * 16 * SNB * 2);
            unsigned ah[2][4], al[2][4];
            #pragma unroll
            for (int mf = 0; mf < 2; mf++) {
                LDSM_X4(ah[mf][0], ah[mf][1], ah[mf][2], ah[mf][3], aAh[mf] + koffA);
                LDSM_X4(al[mf][0], al[mf][1], al[mf][2], al[mf][3], aAl[mf] + koffA);
            }
            unsigned bh[4][2], bl[4][2];
            #pragma unroll
            for (int nf2 = 0; nf2 < 2; nf2++) {
                unsigned r0, r1, r2, r3;
                LDSM_X4T(r0, r1, r2, r3, aBh[nf2] + koffB);
                bh[nf2 * 2][0] = r0;  bh[nf2 * 2][1] = r1;
                bh[nf2 * 2 + 1][0] = r2;  bh[nf2 * 2 + 1][1] = r3;
                LDSM_X4T(r0, r1, r2, r3, aBl[nf2] + koffB);
                bl[nf2 * 2][0] = r0;  bl[nf2 * 2][1] = r1;
                bl[nf2 * 2 + 1][0] = r2;  bl[nf2 * 2 + 1][1] = r3;
            }
            #pragma unroll
            for (int mf = 0; mf < 2; mf++)
                #pragma unroll
                for (int nf = 0; nf < 4; nf++) {
                    MMA_BF16(c[mf][nf], ah[mf], bh[nf]);
                    MMA_BF16(c[mf][nf], ah[mf], bl[nf]);
                    MMA_BF16(c[mf][nf], al[mf], bh[nf]);
                }
        }
    }

    #pragma unroll
    for (int mf = 0; mf < 2; mf++) {
        #pragma unroll
        for (int nf = 0; nf < 4; nf++) {
            int row = m0 + warp_m * 32 + mf * 16 + (lane >> 2);
            int col = n0 + warp_n * 32 + nf * 8 + (lane & 3) * 2;
            float2 b = *(const float2*)(bo + col);
            *(float2*)&out[(size_t)row * DMODEL + col] =
                make_float2(c[mf][nf][0] + b.x, c[mf][nf][1] + b.y);
            *(float2*)&out[(size_t)(row + 8) * DMODEL + col] =
                make_float2(c[mf][nf][2] + b.x, c[mf][nf][3] + b.y);
        }
    }
}

// ---------------------------------------------------------------------------
extern "C" void kernel_launch(void* const* d_in, const int* in_sizes, int n_in,
                              void* d_out, int out_size)
{
    const float* x  = (const float*)d_in[0];
    const float* gm = (const float*)d_in[1];
    const float* Wq = (const float*)d_in[2];
    const float* Wk = (const float*)d_in[3];
    const float* Wv = (const float*)d_in[4];
    const float* Wo = (const float*)d_in[5];
    const float* bo = (const float*)d_in[6];
    float* out = (float*)d_out;

    plan_kernel<<<1, 256>>>(gm);

    dim3 gq(DMODEL / 64, NTOK / 128, 3);
    qkv_gemm<<<gq, 256>>>(x, Wq, Wk, Wv);

    dim3 gg(128, 7, HEADS);
    gather_kernel<<<gg, 320>>>();

    dim3 gm1(HEADS, 16);
    meanv1_kernel<<<gm1, 320>>>();
    meanv2_kernel<<<1, 320>>>();

    dim3 ga(MAXU, HEADS);
    attn_kernel<<<ga, 128>>>();

    reduce_kernel<<<(NTOK * HEADS + 255) / 256, 256>>>();

    dim3 go(DMODEL / 64, NTOK / 128);
    out_gemm<<<go, 256>>>(Wo, bo, out);
}